// round 13
// baseline (speedup 1.0000x reference)
#include <cuda_runtime.h>
#include <cuda_bf16.h>
#include <cstdint>

// ---------------------------------------------------------------------------
// SECONDBackbone: 4 x (3x3x3 conv + masked BN + ReLU), strides 1,2,2,2
// B=2. Channels 4->16->32->64->128. Spatial 32x192x192 -> ... -> 4x24x24.
// Conv: warp = 128 consecutive flat outputs (coalesced loads), thread owns
// p = base+lane+32*o. Register diet: per-output state = base[o] + meta[o]
// (9-bit dh-valid | 3-bit w-valid). __launch_bounds__(128,5) pins ~102 regs
// -> 5 CTAs/SM. Weight smem reuse unchanged (1 LDS.128 -> 16 FMA).
// ---------------------------------------------------------------------------

#define SP0 (32*192*192)   // 1,179,648
#define SP1 (16*96*96)     // 147,456
#define SP2 (8*48*48)      // 18,432
#define SP3 (4*24*24)      // 2,304

// Scratch (device globals; allocation-free kernel_launch)
__device__ float4 g_x4 [2*SP0];             // masked input, ci-interleaved
__device__ float g_y0 [2*16*SP0];
__device__ float g_y1 [2*32*SP1];
__device__ float g_y2 [2*64*SP2];
__device__ float g_y3 [2*128*SP3];
__device__ unsigned char g_m0[2*SP0];
__device__ unsigned char g_m1[2*SP0];
__device__ unsigned char g_m2[2*SP1];
__device__ unsigned char g_m3[2*SP2];
__device__ unsigned char g_m4[2*SP3];
__device__ unsigned char g_mt[2*SP0];       // W-pass temp
__device__ float g_S1[4][128];
__device__ float g_S2[4][128];
__device__ float g_cnt[4];
__device__ float g_cntb[2];
__device__ float g_scale[4][128];
__device__ float g_bias[4][128];

// ---- fused: premask (-> interleaved float4) + mask->uchar + zero stats ----
__global__ void fusedpre_kernel(const float* __restrict__ f,
                                const int* __restrict__ m,
                                float4* __restrict__ x4,
                                unsigned char* __restrict__ m0) {
    int idx = blockIdx.x * 256 + threadIdx.x;      // one thread = 4 voxels
    if (blockIdx.x == 0) {
        int i = threadIdx.x;
        if (i < 128) {
            g_S1[0][i]=0.f; g_S1[1][i]=0.f; g_S1[2][i]=0.f; g_S1[3][i]=0.f;
            g_S2[0][i]=0.f; g_S2[1][i]=0.f; g_S2[2][i]=0.f; g_S2[3][i]=0.f;
        }
        if (i < 4) g_cnt[i] = 0.f;
        if (i < 2) g_cntb[i] = 0.f;
    }
    const int N4 = 2 * SP0 / 4;
    if (idx >= N4) return;
    int sp4 = idx % (SP0 / 4);
    int b   = idx / (SP0 / 4);
    const int4 mi = *(const int4*)(m + (size_t)b * SP0 + (size_t)sp4 * 4);
    uchar4 u;
    u.x = (unsigned char)(mi.x ? 1 : 0);
    u.y = (unsigned char)(mi.y ? 1 : 0);
    u.z = (unsigned char)(mi.z ? 1 : 0);
    u.w = (unsigned char)(mi.w ? 1 : 0);
    ((uchar4*)m0)[idx] = u;
    const float* fb = f + (size_t)b * 4 * SP0 + (size_t)sp4 * 4;
    float4 c0 = *(const float4*)(fb);
    float4 c1 = *(const float4*)(fb + SP0);
    float4 c2 = *(const float4*)(fb + 2 * SP0);
    float4 c3 = *(const float4*)(fb + 3 * SP0);
    float4* xo = x4 + (size_t)b * SP0 + (size_t)sp4 * 4;
    float z0 = mi.x ? 1.f : 0.f, z1 = mi.y ? 1.f : 0.f;
    float z2 = mi.z ? 1.f : 0.f, z3 = mi.w ? 1.f : 0.f;
    xo[0] = make_float4(c0.x*z0, c1.x*z0, c2.x*z0, c3.x*z0);
    xo[1] = make_float4(c0.y*z1, c1.y*z1, c2.y*z1, c3.y*z1);
    xo[2] = make_float4(c0.z*z2, c1.z*z2, c2.z*z2, c3.z*z2);
    xo[3] = make_float4(c0.w*z3, c1.w*z3, c2.w*z3, c3.w*z3);
}

// ------------------- mask maxpool: separable packed OR ---------------------
template<int S, int WI, int WO>
__global__ void maskW_kernel(const unsigned char* __restrict__ min,
                             unsigned char* __restrict__ wt, int nRows) {
    const int WPR = WO / 4;
    int idx = blockIdx.x * 256 + threadIdx.x;
    if (idx >= nRows * WPR) return;
    int k = idx % WPR;
    int rowid = idx / WPR;
    const unsigned char* row = min + (size_t)rowid * WI;
    unsigned out;
    if (S == 1) {
        unsigned x  = ((const unsigned*)row)[k];
        unsigned lb = (k > 0)          ? row[4*k - 1] : 0u;
        unsigned rb = (4*k + 4 < WI)   ? row[4*k + 4] : 0u;
        out = x | ((x << 8) | lb) | ((x >> 8) | (rb << 24));
    } else {
        unsigned x0 = ((const unsigned*)row)[2*k];
        unsigned x1 = ((const unsigned*)row)[2*k + 1];
        unsigned long long v  = ((unsigned long long)x1 << 32) | x0;
        unsigned long long lb = (k > 0) ? (unsigned long long)row[8*k - 1] : 0ull;
        unsigned long long t  = v | (v >> 8) | ((v << 8) | lb);
        out = __byte_perm((unsigned)t, (unsigned)(t >> 32), 0x6420);
    }
    ((unsigned*)wt)[idx] = out;
}

template<int S, int DI, int HI, int DO, int HO, int WO, bool PB>
__global__ void maskDH_kernel(const unsigned char* __restrict__ wt,
                              unsigned char* __restrict__ mout,
                              float* __restrict__ cnt,
                              float* __restrict__ cntb) {
    const int WPR = WO / 4;
    const int N = 2 * DO * HO * WPR;
    int idx = blockIdx.x * 256 + threadIdx.x;
    bool act = idx < N;
    unsigned acc = 0;
    int b = 0;
    if (act) {
        int k  = idx % WPR;
        int r  = idx / WPR;
        int ho = r % HO;
        int r2 = r / HO;
        int dO = r2 % DO;
        b      = r2 / DO;
        int d0 = dO * S - 1, h0 = ho * S - 1;
        #pragma unroll
        for (int kd = 0; kd < 3; kd++) {
            int di = d0 + kd; if ((unsigned)di >= (unsigned)DI) continue;
            #pragma unroll
            for (int kh = 0; kh < 3; kh++) {
                int hi = h0 + kh; if ((unsigned)hi >= (unsigned)HI) continue;
                acc |= ((const unsigned*)(wt +
                        (((size_t)(b * DI + di)) * HI + hi) * WO))[k];
            }
        }
        ((unsigned*)mout)[idx] = acc;
    }
    int c = act ? __popc(acc) : 0;
    #pragma unroll
    for (int off = 16; off > 0; off >>= 1)
        c += __shfl_down_sync(0xffffffffu, c, off);
    if ((threadIdx.x & 31) == 0 && c) {
        atomicAdd(cnt, (float)c);
        if (PB) atomicAdd(&cntb[b], (float)c);
    }
}

// per-output validity meta: bits[0:9) = (kd*3+kh) row valid, bits[9:12) = kw valid
template<int S, int DI, int HI, int WI>
__device__ __forceinline__ unsigned make_meta(int d, int h, int w) {
    unsigned mD = (((unsigned)(d*S-1) < (unsigned)DI) ? 1u : 0u)
                | (((unsigned)(d*S  ) < (unsigned)DI) ? 2u : 0u)
                | (((unsigned)(d*S+1) < (unsigned)DI) ? 4u : 0u);
    unsigned mH = (((unsigned)(h*S-1) < (unsigned)HI) ? 1u : 0u)
                | (((unsigned)(h*S  ) < (unsigned)HI) ? 2u : 0u)
                | (((unsigned)(h*S+1) < (unsigned)HI) ? 4u : 0u);
    unsigned mW = (((unsigned)(w*S-1) < (unsigned)WI) ? 1u : 0u)
                | (((unsigned)(w*S  ) < (unsigned)WI) ? 2u : 0u)
                | (((unsigned)(w*S+1) < (unsigned)WI) ? 4u : 0u);
    unsigned v9 = ((mD & 1u) ? mH : 0u)
                | ((mD & 2u) ? (mH << 3) : 0u)
                | ((mD & 4u) ? (mH << 6) : 0u);
    return v9 | (mW << 9);
}

// ------- conv0: CIN=4 interleaved float4, coalesced interleaved T=4 --------
__global__ __launch_bounds__(128, 5)
void conv0_kernel(const float4* __restrict__ x4,
                  const unsigned char* __restrict__ mo,
                  const float* __restrict__ wglob,
                  float* __restrict__ y,
                  float* __restrict__ S1g,
                  float* __restrict__ S2g) {
    constexpr int DI=32, HI=192, WI=192, HO=192, WO=192;
    constexpr int T = 4, CO_TILE = 8, VPT = 4;
    constexpr int SPI = HI * WI;
    constexpr int SPO = DI * SPI;

    __shared__ float ws[27*4*CO_TILE];
    __shared__ float red[2*CO_TILE];
    const int tid = threadIdx.x, wid = tid >> 5, lane = tid & 31;
    const int b = blockIdx.z;
    const int coBase = blockIdx.y * CO_TILE;

    for (int i = tid; i < 27*4*CO_TILE; i += 128) {
        int co = i % CO_TILE;
        int rest = i / CO_TILE;
        int ci = rest % 4;
        int k  = rest / 4;
        ws[i] = wglob[((size_t)(coBase + co) * 4 + ci) * 27 + k];
    }
    if (tid < 2*CO_TILE) red[tid] = 0.f;
    __syncthreads();

    const float4* xb = x4 + (size_t)b * SPO;
    const unsigned char* mb = mo + (size_t)b * SPO;

    float s1[CO_TILE], s2[CO_TILE];
    #pragma unroll
    for (int j = 0; j < CO_TILE; j++) { s1[j] = 0.f; s2[j] = 0.f; }

    #pragma unroll 1
    for (int v = 0; v < VPT; ++v) {
        int blk = (blockIdx.x * VPT + v) * 4 + wid;
        int base[T]; unsigned meta[T];
        #pragma unroll
        for (int o = 0; o < T; o++) {
            int pp = blk * 128 + lane + 32 * o;
            int w = pp % WO;
            int t1 = pp / WO;
            int h = t1 % HO;
            int d = t1 / HO;
            base[o] = (d - 1) * SPI + (h - 1) * WI + (w - 1);
            meta[o] = make_meta<1, DI, HI, WI>(d, h, w);
        }

        float acc[T][CO_TILE];
        #pragma unroll
        for (int o = 0; o < T; o++)
            #pragma unroll
            for (int j = 0; j < CO_TILE; j++) acc[o][j] = 0.f;

        #pragma unroll
        for (int kd = 0; kd < 3; kd++) {
            #pragma unroll
            for (int kh = 0; kh < 3; kh++) {
                const float* wt = ws + (kd*3 + kh) * 3 * (4*CO_TILE);
                #pragma unroll
                for (int kw = 0; kw < 3; kw++) {
                    float4 xq[T];
                    #pragma unroll
                    for (int o = 0; o < T; o++) {
                        bool vv = (meta[o] >> (kd*3 + kh)) & (meta[o] >> (9 + kw)) & 1u;
                        xq[o] = vv ? __ldg(xb + base[o] + kd * SPI + kh * WI + kw)
                                   : make_float4(0.f, 0.f, 0.f, 0.f);
                    }
                    #pragma unroll
                    for (int ci = 0; ci < 4; ci++) {
                        const float4* wv = (const float4*)(wt + kw * (4*CO_TILE) + ci * CO_TILE);
                        float xx[T];
                        #pragma unroll
                        for (int o = 0; o < T; o++)
                            xx[o] = (ci == 0) ? xq[o].x : (ci == 1) ? xq[o].y
                                  : (ci == 2) ? xq[o].z : xq[o].w;
                        #pragma unroll
                        for (int j = 0; j < CO_TILE/4; j++) {
                            float4 w4 = wv[j];
                            #pragma unroll
                            for (int o = 0; o < T; o++) {
                                acc[o][4*j+0] += xx[o] * w4.x;
                                acc[o][4*j+1] += xx[o] * w4.y;
                                acc[o][4*j+2] += xx[o] * w4.z;
                                acc[o][4*j+3] += xx[o] * w4.w;
                            }
                        }
                    }
                }
            }
        }

        #pragma unroll
        for (int o = 0; o < T; o++) {
            int pp = blk * 128 + lane + 32 * o;
            float mval = mb[pp] ? 1.f : 0.f;
            float* yb = y + (size_t)(b * 16 + coBase) * SPO + pp;
            #pragma unroll
            for (int j = 0; j < CO_TILE; j++) {
                float a = acc[o][j];
                yb[(size_t)j * SPO] = a;
                float am = a * mval;
                s1[j] += am;
                s2[j] += am * a;
            }
        }
    }

    #pragma unroll
    for (int j = 0; j < CO_TILE; j++) {
        float v1 = s1[j], v2 = s2[j];
        #pragma unroll
        for (int off = 16; off > 0; off >>= 1) {
            v1 += __shfl_down_sync(0xffffffffu, v1, off);
            v2 += __shfl_down_sync(0xffffffffu, v2, off);
        }
        if (lane == 0) {
            atomicAdd(&red[j], v1);
            atomicAdd(&red[CO_TILE + j], v2);
        }
    }
    __syncthreads();
    if (tid < CO_TILE) {
        atomicAdd(&S1g[coBase + tid], red[tid]);
        atomicAdd(&S2g[coBase + tid], red[CO_TILE + tid]);
    }
}

// ------ generic conv (planar input), coalesced interleaved T=4, any S ------
template<int CIN, int COUT, int CO_TILE, int S,
         int DI, int HI, int WI, int DO, int HO, int WO, int VPT>
__global__ __launch_bounds__(128, 5)
void conv_kernel(const float* __restrict__ x,
                 const unsigned char* __restrict__ mo,
                 const float* __restrict__ wglob,
                 float* __restrict__ y,
                 float* __restrict__ S1g,
                 float* __restrict__ S2g) {
    constexpr int T = 4;
    constexpr int SPO = DO * HO * WO;
    constexpr int SPI = HI * WI;

    extern __shared__ float sh[];
    float* ws  = sh;
    float* red = sh + 27 * CIN * CO_TILE;
    const int tid = threadIdx.x, wid = tid >> 5, lane = tid & 31;
    const int b = blockIdx.z;
    const int coBase = blockIdx.y * CO_TILE;

    for (int i = tid; i < 27 * CIN * CO_TILE; i += 128) {
        int co = i % CO_TILE;
        int rest = i / CO_TILE;
        int ci = rest % CIN;
        int k  = rest / CIN;
        ws[i] = wglob[((size_t)(coBase + co) * CIN + ci) * 27 + k];
    }
    if (tid < 2 * CO_TILE) red[tid] = 0.f;
    __syncthreads();

    const float* xb = x + (size_t)b * CIN * DI * SPI;
    const unsigned char* mb = mo + (size_t)b * SPO;

    float s1[CO_TILE], s2[CO_TILE];
    #pragma unroll
    for (int j = 0; j < CO_TILE; j++) { s1[j] = 0.f; s2[j] = 0.f; }

    #pragma unroll 1
    for (int v = 0; v < VPT; ++v) {
        int blk = (blockIdx.x * VPT + v) * 4 + wid;
        if (blk * 128 >= SPO) break;
        int base[T]; unsigned meta[T];
        #pragma unroll
        for (int o = 0; o < T; o++) {
            int pp = blk * 128 + lane + 32 * o;
            int w = pp % WO;
            int t1 = pp / WO;
            int h = t1 % HO;
            int d = t1 / HO;
            base[o] = (d * S - 1) * SPI + (h * S - 1) * WI + (w * S - 1);
            meta[o] = make_meta<S, DI, HI, WI>(d, h, w);
        }

        float acc[T][CO_TILE];
        #pragma unroll
        for (int o = 0; o < T; o++)
            #pragma unroll
            for (int j = 0; j < CO_TILE; j++) acc[o][j] = 0.f;

        #pragma unroll
        for (int kd = 0; kd < 3; kd++) {
            #pragma unroll
            for (int kh = 0; kh < 3; kh++) {
                const float* wt = ws + (kd*3 + kh) * 3 * (CIN * CO_TILE);
                #pragma unroll 4
                for (int ci = 0; ci < CIN; ci++) {
                    const float* xr = xb + (size_t)ci * (DI * SPI);
                    #pragma unroll
                    for (int kw = 0; kw < 3; kw++) {
                        float xx[T];
                        #pragma unroll
                        for (int o = 0; o < T; o++) {
                            bool vv = (meta[o] >> (kd*3 + kh)) & (meta[o] >> (9 + kw)) & 1u;
                            xx[o] = vv ? __ldg(xr + base[o] + kd * SPI + kh * WI + kw) : 0.f;
                        }
                        const float4* wv = (const float4*)(wt + kw * (CIN*CO_TILE) + ci * CO_TILE);
                        #pragma unroll
                        for (int j = 0; j < CO_TILE / 4; j++) {
                            float4 w4 = wv[j];
                            #pragma unroll
                            for (int o = 0; o < T; o++) {
                                acc[o][4*j+0] += xx[o] * w4.x;
                                acc[o][4*j+1] += xx[o] * w4.y;
                                acc[o][4*j+2] += xx[o] * w4.z;
                                acc[o][4*j+3] += xx[o] * w4.w;
                            }
                        }
                    }
                }
            }
        }

        #pragma unroll
        for (int o = 0; o < T; o++) {
            int pp = blk * 128 + lane + 32 * o;
            float mval = mb[pp] ? 1.f : 0.f;
            float* yb = y + (size_t)(b * COUT + coBase) * SPO + pp;
            #pragma unroll
            for (int j = 0; j < CO_TILE; j++) {
                float a = acc[o][j];
                yb[(size_t)j * SPO] = a;
                float am = a * mval;
                s1[j] += am;
                s2[j] += am * a;
            }
        }
    }

    #pragma unroll
    for (int j = 0; j < CO_TILE; j++) {
        float v1 = s1[j], v2 = s2[j];
        #pragma unroll
        for (int off = 16; off > 0; off >>= 1) {
            v1 += __shfl_down_sync(0xffffffffu, v1, off);
            v2 += __shfl_down_sync(0xffffffffu, v2, off);
        }
        if (lane == 0) {
            atomicAdd(&red[j], v1);
            atomicAdd(&red[CO_TILE + j], v2);
        }
    }
    __syncthreads();
    if (tid < CO_TILE) {
        atomicAdd(&S1g[coBase + tid], red[tid]);
        atomicAdd(&S2g[coBase + tid], red[CO_TILE + tid]);
    }
}

// --------------------------- BN finalize -----------------------------------
__global__ void finalize_kernel(const float* __restrict__ S1,
                                const float* __restrict__ S2,
                                const float* __restrict__ cnt,
                                const float* __restrict__ g,
                                const float* __restrict__ bt,
                                float* __restrict__ scale,
                                float* __restrict__ bias, int C) {
    int c = threadIdx.x;
    if (c < C) {
        float n = fmaxf(*cnt, 1.f);
        float mean = S1[c] / n;
        float var = S2[c] / n - mean * mean;
        var = fmaxf(var, 0.f);
        float sc = g[c] * rsqrtf(var + 1e-5f);
        scale[c] = sc;
        bias[c] = bt[c] - mean * sc;
    }
}

// ----------------- BN apply + relu + mask (float4) -------------------------
template<int COUT, int SPO>
__global__ void bnrelu_kernel(const float* __restrict__ y,
                              const unsigned char* __restrict__ mo,
                              const float* __restrict__ scale,
                              const float* __restrict__ bias,
                              float* __restrict__ xout) {
    int idx = blockIdx.x * 256 + threadIdx.x;
    const int N4 = 2 * COUT * SPO / 4;
    if (idx >= N4) return;
    int sp4 = idx % (SPO / 4);
    int bc  = idx / (SPO / 4);
    int c   = bc % COUT;
    int b   = bc / COUT;
    uchar4 m4 = *(const uchar4*)(mo + (size_t)b * SPO + (size_t)sp4 * 4);
    float4 v = ((const float4*)y)[idx];
    float sc = scale[c], bi = bias[c];
    v.x = m4.x ? fmaxf(v.x * sc + bi, 0.f) : 0.f;
    v.y = m4.y ? fmaxf(v.y * sc + bi, 0.f) : 0.f;
    v.z = m4.z ? fmaxf(v.z * sc + bi, 0.f) : 0.f;
    v.w = m4.w ? fmaxf(v.w * sc + bi, 0.f) : 0.f;
    ((float4*)xout)[idx] = v;
}

// --------------------------- global masked pooling -------------------------
__global__ void pool_kernel(const float* __restrict__ x,
                            const float* __restrict__ cntb,
                            float* __restrict__ gf) {
    __shared__ float sm[256];
    int bc = blockIdx.x;
    int b = bc / 128;
    const float* p = x + (size_t)bc * SP3;
    float s = 0.f;
    for (int i = threadIdx.x; i < SP3; i += 256) s += p[i];
    sm[threadIdx.x] = s;
    __syncthreads();
    for (int off = 128; off > 0; off >>= 1) {
        if (threadIdx.x < off) sm[threadIdx.x] += sm[threadIdx.x + off];
        __syncthreads();
    }
    if (threadIdx.x == 0) gf[bc] = sm[0] / fmaxf(cntb[b], 1.f);
}

// ---------------------------------------------------------------------------
extern "C" void kernel_launch(void* const* d_in, const int* in_sizes, int n_in,
                              void* d_out, int out_size) {
    const float* features = (const float*)d_in[0];
    const int*   mask     = (const int*)d_in[1];
    const float* w0 = (const float*)d_in[2];
    const float* gg0 = (const float*)d_in[3];
    const float* bb0 = (const float*)d_in[4];
    const float* w1 = (const float*)d_in[5];
    const float* gg1 = (const float*)d_in[6];
    const float* bb1 = (const float*)d_in[7];
    const float* w2 = (const float*)d_in[8];
    const float* gg2 = (const float*)d_in[9];
    const float* bb2 = (const float*)d_in[10];
    const float* w3 = (const float*)d_in[11];
    const float* gg3 = (const float*)d_in[12];
    const float* bb3 = (const float*)d_in[13];
    float* out = (float*)d_out;

    void* p;
    cudaGetSymbolAddress(&p, g_x4);   float4* x4 = (float4*)p;
    cudaGetSymbolAddress(&p, g_y0);   float* y0  = (float*)p;
    cudaGetSymbolAddress(&p, g_y1);   float* y1  = (float*)p;
    cudaGetSymbolAddress(&p, g_y2);   float* y2  = (float*)p;
    cudaGetSymbolAddress(&p, g_y3);   float* y3  = (float*)p;
    cudaGetSymbolAddress(&p, g_m0);   unsigned char* m0 = (unsigned char*)p;
    cudaGetSymbolAddress(&p, g_m1);   unsigned char* m1 = (unsigned char*)p;
    cudaGetSymbolAddress(&p, g_m2);   unsigned char* m2 = (unsigned char*)p;
    cudaGetSymbolAddress(&p, g_m3);   unsigned char* m3 = (unsigned char*)p;
    cudaGetSymbolAddress(&p, g_m4);   unsigned char* m4 = (unsigned char*)p;
    cudaGetSymbolAddress(&p, g_mt);   unsigned char* mt = (unsigned char*)p;
    cudaGetSymbolAddress(&p, g_S1);   float* S1 = (float*)p;
    cudaGetSymbolAddress(&p, g_S2);   float* S2 = (float*)p;
    cudaGetSymbolAddress(&p, g_cnt);  float* cnt = (float*)p;
    cudaGetSymbolAddress(&p, g_cntb); float* cntb = (float*)p;
    cudaGetSymbolAddress(&p, g_scale);float* scale = (float*)p;
    cudaGetSymbolAddress(&p, g_bias); float* bias  = (float*)p;

    // (1) fused premask + mask->uchar + stats zero
    fusedpre_kernel<<<(2*SP0/4 + 255) / 256, 256>>>(features, mask, x4, m0);

    // ---------------- block 0: 4 -> 16, stride 1 ----------------
    maskW_kernel<1,192,192><<<(2*32*192*48 + 255)/256, 256>>>(m0, mt, 2*32*192);
    maskDH_kernel<1,32,192,32,192,192,false>
        <<<(2*32*192*48 + 255)/256, 256>>>(mt, m1, &cnt[0], cntb);
    // warp-blocks per batch image = SP0/128 = 9216; grid.x = 9216/(4*VPT=16) = 576
    conv0_kernel<<<dim3(576, 2, 2), 128>>>(x4, m1, w0, y0, &S1[0], &S2[0]);
    finalize_kernel<<<1, 128>>>(&S1[0], &S2[0], &cnt[0], gg0, bb0,
                                &scale[0], &bias[0], 16);
    bnrelu_kernel<16, SP0><<<(2*16*SP0/4 + 255)/256, 256>>>(y0, m1, &scale[0], &bias[0], y0);

    // ---------------- block 1: 16 -> 32, stride 2 ----------------
    maskW_kernel<2,192,96><<<(2*32*192*24 + 255)/256, 256>>>(m1, mt, 2*32*192);
    maskDH_kernel<2,32,192,16,96,96,false>
        <<<(2*16*96*24 + 255)/256, 256>>>(mt, m2, &cnt[1], cntb);
    // warp-blocks = SP1/128 = 1152; VPT=2 -> grid.x = 1152/8 = 144
    conv_kernel<16,32,8,2,32,192,192,16,96,96,2>
        <<<dim3(144, 4, 2), 128, (27*16*8 + 16)*4>>>(
            y0, m2, w1, y1, &S1[128], &S2[128]);
    finalize_kernel<<<1, 128>>>(&S1[128], &S2[128], &cnt[1], gg1, bb1,
                                &scale[128], &bias[128], 32);
    bnrelu_kernel<32, SP1><<<(2*32*SP1/4 + 255)/256, 256>>>(y1, m2, &scale[128], &bias[128], y1);

    // ---------------- block 2: 32 -> 64, stride 2 ----------------
    maskW_kernel<2,96,48><<<(2*16*96*12 + 255)/256, 256>>>(m2, mt, 2*16*96);
    maskDH_kernel<2,16,96,8,48,48,false>
        <<<(2*8*48*12 + 255)/256, 256>>>(mt, m3, &cnt[2], cntb);
    // warp-blocks = SP2/128 = 144; VPT=1 -> grid.x = 36
    conv_kernel<32,64,8,2,16,96,96,8,48,48,1>
        <<<dim3(36, 8, 2), 128, (27*32*8 + 16)*4>>>(
            y1, m3, w2, y2, &S1[256], &S2[256]);
    finalize_kernel<<<1, 128>>>(&S1[256], &S2[256], &cnt[2], gg2, bb2,
                                &scale[256], &bias[256], 64);
    bnrelu_kernel<64, SP2><<<(2*64*SP2/4 + 255)/256, 256>>>(y2, m3, &scale[256], &bias[256], y2);

    // ---------------- block 3: 64 -> 128, stride 2 ----------------
    maskW_kernel<2,48,24><<<(2*8*48*6 + 255)/256, 256>>>(m3, mt, 2*8*48);
    maskDH_kernel<2,8,48,4,24,24,true>
        <<<(2*4*24*6 + 255)/256, 256>>>(mt, m4, &cnt[3], cntb);
    // warp-blocks = SP3/128 = 18; VPT=1 -> grid.x = ceil(18/4) = 5 (guarded)
    conv_kernel<64,128,4,2,8,48,48,4,24,24,1>
        <<<dim3(5, 32, 2), 128, (27*64*4 + 8)*4>>>(
            y2, m4, w3, y3, &S1[384], &S2[384]);
    finalize_kernel<<<1, 128>>>(&S1[384], &S2[384], &cnt[3], gg3, bb3,
                                &scale[384], &bias[384], 128);
    bnrelu_kernel<128, SP3><<<(2*128*SP3/4 + 255)/256, 256>>>(y3, m4, &scale[384], &bias[384], out);

    // ---------------- global pooling ----------------
    pool_kernel<<<256, 256>>>(out, cntb, out + 2*128*SP3);
}

// round 14
// speedup vs baseline: 1.2172x; 1.2172x over previous
#include <cuda_runtime.h>
#include <cuda_bf16.h>
#include <cstdint>

// ---------------------------------------------------------------------------
// SECONDBackbone: 4 x (3x3x3 conv + masked BN + ReLU), strides 1,2,2,2
// B=2. Channels 4->16->32->64->128. Spatial 32x192x192 -> ... -> 4x24x24.
// Conv: warp = 128 consecutive flat outputs (coalesced loads), thread owns
// p = base+lane+32*o. R12 body + mild reg cap __launch_bounds__(128,4)
// (precomputed predicate bools retained — no per-load ALU decode).
// ---------------------------------------------------------------------------

#define SP0 (32*192*192)   // 1,179,648
#define SP1 (16*96*96)     // 147,456
#define SP2 (8*48*48)      // 18,432
#define SP3 (4*24*24)      // 2,304

// Scratch (device globals; allocation-free kernel_launch)
__device__ float4 g_x4 [2*SP0];             // masked input, ci-interleaved
__device__ float g_y0 [2*16*SP0];
__device__ float g_y1 [2*32*SP1];
__device__ float g_y2 [2*64*SP2];
__device__ float g_y3 [2*128*SP3];
__device__ unsigned char g_m0[2*SP0];
__device__ unsigned char g_m1[2*SP0];
__device__ unsigned char g_m2[2*SP1];
__device__ unsigned char g_m3[2*SP2];
__device__ unsigned char g_m4[2*SP3];
__device__ unsigned char g_mt[2*SP0];       // W-pass temp
__device__ float g_S1[4][128];
__device__ float g_S2[4][128];
__device__ float g_cnt[4];
__device__ float g_cntb[2];
__device__ float g_scale[4][128];
__device__ float g_bias[4][128];

// ---- fused: premask (-> interleaved float4) + mask->uchar + zero stats ----
__global__ void fusedpre_kernel(const float* __restrict__ f,
                                const int* __restrict__ m,
                                float4* __restrict__ x4,
                                unsigned char* __restrict__ m0) {
    int idx = blockIdx.x * 256 + threadIdx.x;      // one thread = 4 voxels
    if (blockIdx.x == 0) {
        int i = threadIdx.x;
        if (i < 128) {
            g_S1[0][i]=0.f; g_S1[1][i]=0.f; g_S1[2][i]=0.f; g_S1[3][i]=0.f;
            g_S2[0][i]=0.f; g_S2[1][i]=0.f; g_S2[2][i]=0.f; g_S2[3][i]=0.f;
        }
        if (i < 4) g_cnt[i] = 0.f;
        if (i < 2) g_cntb[i] = 0.f;
    }
    const int N4 = 2 * SP0 / 4;
    if (idx >= N4) return;
    int sp4 = idx % (SP0 / 4);
    int b   = idx / (SP0 / 4);
    const int4 mi = *(const int4*)(m + (size_t)b * SP0 + (size_t)sp4 * 4);
    uchar4 u;
    u.x = (unsigned char)(mi.x ? 1 : 0);
    u.y = (unsigned char)(mi.y ? 1 : 0);
    u.z = (unsigned char)(mi.z ? 1 : 0);
    u.w = (unsigned char)(mi.w ? 1 : 0);
    ((uchar4*)m0)[idx] = u;
    const float* fb = f + (size_t)b * 4 * SP0 + (size_t)sp4 * 4;
    float4 c0 = *(const float4*)(fb);
    float4 c1 = *(const float4*)(fb + SP0);
    float4 c2 = *(const float4*)(fb + 2 * SP0);
    float4 c3 = *(const float4*)(fb + 3 * SP0);
    float4* xo = x4 + (size_t)b * SP0 + (size_t)sp4 * 4;
    float z0 = mi.x ? 1.f : 0.f, z1 = mi.y ? 1.f : 0.f;
    float z2 = mi.z ? 1.f : 0.f, z3 = mi.w ? 1.f : 0.f;
    xo[0] = make_float4(c0.x*z0, c1.x*z0, c2.x*z0, c3.x*z0);
    xo[1] = make_float4(c0.y*z1, c1.y*z1, c2.y*z1, c3.y*z1);
    xo[2] = make_float4(c0.z*z2, c1.z*z2, c2.z*z2, c3.z*z2);
    xo[3] = make_float4(c0.w*z3, c1.w*z3, c2.w*z3, c3.w*z3);
}

// ------------------- mask maxpool: separable packed OR ---------------------
template<int S, int WI, int WO>
__global__ void maskW_kernel(const unsigned char* __restrict__ min,
                             unsigned char* __restrict__ wt, int nRows) {
    const int WPR = WO / 4;
    int idx = blockIdx.x * 256 + threadIdx.x;
    if (idx >= nRows * WPR) return;
    int k = idx % WPR;
    int rowid = idx / WPR;
    const unsigned char* row = min + (size_t)rowid * WI;
    unsigned out;
    if (S == 1) {
        unsigned x  = ((const unsigned*)row)[k];
        unsigned lb = (k > 0)          ? row[4*k - 1] : 0u;
        unsigned rb = (4*k + 4 < WI)   ? row[4*k + 4] : 0u;
        out = x | ((x << 8) | lb) | ((x >> 8) | (rb << 24));
    } else {
        unsigned x0 = ((const unsigned*)row)[2*k];
        unsigned x1 = ((const unsigned*)row)[2*k + 1];
        unsigned long long v  = ((unsigned long long)x1 << 32) | x0;
        unsigned long long lb = (k > 0) ? (unsigned long long)row[8*k - 1] : 0ull;
        unsigned long long t  = v | (v >> 8) | ((v << 8) | lb);
        out = __byte_perm((unsigned)t, (unsigned)(t >> 32), 0x6420);
    }
    ((unsigned*)wt)[idx] = out;
}

template<int S, int DI, int HI, int DO, int HO, int WO, bool PB>
__global__ void maskDH_kernel(const unsigned char* __restrict__ wt,
                              unsigned char* __restrict__ mout,
                              float* __restrict__ cnt,
                              float* __restrict__ cntb) {
    const int WPR = WO / 4;
    const int N = 2 * DO * HO * WPR;
    int idx = blockIdx.x * 256 + threadIdx.x;
    bool act = idx < N;
    unsigned acc = 0;
    int b = 0;
    if (act) {
        int k  = idx % WPR;
        int r  = idx / WPR;
        int ho = r % HO;
        int r2 = r / HO;
        int dO = r2 % DO;
        b      = r2 / DO;
        int d0 = dO * S - 1, h0 = ho * S - 1;
        #pragma unroll
        for (int kd = 0; kd < 3; kd++) {
            int di = d0 + kd; if ((unsigned)di >= (unsigned)DI) continue;
            #pragma unroll
            for (int kh = 0; kh < 3; kh++) {
                int hi = h0 + kh; if ((unsigned)hi >= (unsigned)HI) continue;
                acc |= ((const unsigned*)(wt +
                        (((size_t)(b * DI + di)) * HI + hi) * WO))[k];
            }
        }
        ((unsigned*)mout)[idx] = acc;
    }
    int c = act ? __popc(acc) : 0;
    #pragma unroll
    for (int off = 16; off > 0; off >>= 1)
        c += __shfl_down_sync(0xffffffffu, c, off);
    if ((threadIdx.x & 31) == 0 && c) {
        atomicAdd(cnt, (float)c);
        if (PB) atomicAdd(&cntb[b], (float)c);
    }
}

// ------- conv0: CIN=4 interleaved float4, coalesced interleaved T=4 --------
__global__ __launch_bounds__(128, 4)
void conv0_kernel(const float4* __restrict__ x4,
                  const unsigned char* __restrict__ mo,
                  const float* __restrict__ wglob,
                  float* __restrict__ y,
                  float* __restrict__ S1g,
                  float* __restrict__ S2g) {
    constexpr int DI=32, HI=192, WI=192, HO=192, WO=192;
    constexpr int T = 4, CO_TILE = 8, VPT = 4;
    constexpr int SPI = HI * WI;
    constexpr int SPO = DI * SPI;

    __shared__ float ws[27*4*CO_TILE];
    __shared__ float red[2*CO_TILE];
    const int tid = threadIdx.x, wid = tid >> 5, lane = tid & 31;
    const int b = blockIdx.z;
    const int coBase = blockIdx.y * CO_TILE;

    for (int i = tid; i < 27*4*CO_TILE; i += 128) {
        int co = i % CO_TILE;
        int rest = i / CO_TILE;
        int ci = rest % 4;
        int k  = rest / 4;
        ws[i] = wglob[((size_t)(coBase + co) * 4 + ci) * 27 + k];
    }
    if (tid < 2*CO_TILE) red[tid] = 0.f;
    __syncthreads();

    const float4* xb = x4 + (size_t)b * SPO;
    const unsigned char* mb = mo + (size_t)b * SPO;

    float s1[CO_TILE], s2[CO_TILE];
    #pragma unroll
    for (int j = 0; j < CO_TILE; j++) { s1[j] = 0.f; s2[j] = 0.f; }

    #pragma unroll 1
    for (int v = 0; v < VPT; ++v) {
        int blk = (blockIdx.x * VPT + v) * 4 + wid;
        int base0[T], h0a[T], d0a[T];
        bool vw0[T], vw2[T];
        #pragma unroll
        for (int o = 0; o < T; o++) {
            int pp = blk * 128 + lane + 32 * o;
            int w = pp % WO;
            int t1 = pp / WO;
            int h = t1 % HO;
            int d = t1 / HO;
            d0a[o] = d - 1;
            h0a[o] = h - 1;
            base0[o] = (d - 1) * SPI + (h - 1) * WI + (w - 1);
            vw0[o] = (w > 0);
            vw2[o] = (w < WO - 1);
        }

        float acc[T][CO_TILE];
        #pragma unroll
        for (int o = 0; o < T; o++)
            #pragma unroll
            for (int j = 0; j < CO_TILE; j++) acc[o][j] = 0.f;

        #pragma unroll
        for (int kd = 0; kd < 3; kd++) {
            #pragma unroll
            for (int kh = 0; kh < 3; kh++) {
                int rb[T]; bool rv[T];
                #pragma unroll
                for (int o = 0; o < T; o++) {
                    rv[o] = ((unsigned)(d0a[o] + kd) < (unsigned)DI) &&
                            ((unsigned)(h0a[o] + kh) < (unsigned)HI);
                    rb[o] = base0[o] + kd * SPI + kh * WI;
                }
                const float* wt = ws + (kd*3 + kh) * 3 * (4*CO_TILE);
                #pragma unroll
                for (int kw = 0; kw < 3; kw++) {
                    float4 xq[T];
                    #pragma unroll
                    for (int o = 0; o < T; o++) {
                        bool vv = rv[o] && (kw == 1 || (kw == 0 ? vw0[o] : vw2[o]));
                        xq[o] = vv ? __ldg(xb + rb[o] + kw)
                                   : make_float4(0.f, 0.f, 0.f, 0.f);
                    }
                    #pragma unroll
                    for (int ci = 0; ci < 4; ci++) {
                        const float4* wv = (const float4*)(wt + kw * (4*CO_TILE) + ci * CO_TILE);
                        float xx[T];
                        #pragma unroll
                        for (int o = 0; o < T; o++)
                            xx[o] = (ci == 0) ? xq[o].x : (ci == 1) ? xq[o].y
                                  : (ci == 2) ? xq[o].z : xq[o].w;
                        #pragma unroll
                        for (int j = 0; j < CO_TILE/4; j++) {
                            float4 w4 = wv[j];
                            #pragma unroll
                            for (int o = 0; o < T; o++) {
                                acc[o][4*j+0] += xx[o] * w4.x;
                                acc[o][4*j+1] += xx[o] * w4.y;
                                acc[o][4*j+2] += xx[o] * w4.z;
                                acc[o][4*j+3] += xx[o] * w4.w;
                            }
                        }
                    }
                }
            }
        }

        #pragma unroll
        for (int o = 0; o < T; o++) {
            int pp = blk * 128 + lane + 32 * o;
            float mval = mb[pp] ? 1.f : 0.f;
            float* yb = y + (size_t)(b * 16 + coBase) * SPO + pp;
            #pragma unroll
            for (int j = 0; j < CO_TILE; j++) {
                float a = acc[o][j];
                yb[(size_t)j * SPO] = a;
                float am = a * mval;
                s1[j] += am;
                s2[j] += am * a;
            }
        }
    }

    #pragma unroll
    for (int j = 0; j < CO_TILE; j++) {
        float v1 = s1[j], v2 = s2[j];
        #pragma unroll
        for (int off = 16; off > 0; off >>= 1) {
            v1 += __shfl_down_sync(0xffffffffu, v1, off);
            v2 += __shfl_down_sync(0xffffffffu, v2, off);
        }
        if (lane == 0) {
            atomicAdd(&red[j], v1);
            atomicAdd(&red[CO_TILE + j], v2);
        }
    }
    __syncthreads();
    if (tid < CO_TILE) {
        atomicAdd(&S1g[coBase + tid], red[tid]);
        atomicAdd(&S2g[coBase + tid], red[CO_TILE + tid]);
    }
}

// ------ generic conv (planar input), coalesced interleaved T=4, any S ------
template<int CIN, int COUT, int CO_TILE, int S,
         int DI, int HI, int WI, int DO, int HO, int WO, int VPT>
__global__ __launch_bounds__(128, 4)
void conv_kernel(const float* __restrict__ x,
                 const unsigned char* __restrict__ mo,
                 const float* __restrict__ wglob,
                 float* __restrict__ y,
                 float* __restrict__ S1g,
                 float* __restrict__ S2g) {
    constexpr int T = 4;
    constexpr int SPO = DO * HO * WO;
    constexpr int SPI = HI * WI;

    extern __shared__ float sh[];
    float* ws  = sh;
    float* red = sh + 27 * CIN * CO_TILE;
    const int tid = threadIdx.x, wid = tid >> 5, lane = tid & 31;
    const int b = blockIdx.z;
    const int coBase = blockIdx.y * CO_TILE;

    for (int i = tid; i < 27 * CIN * CO_TILE; i += 128) {
        int co = i % CO_TILE;
        int rest = i / CO_TILE;
        int ci = rest % CIN;
        int k  = rest / CIN;
        ws[i] = wglob[((size_t)(coBase + co) * CIN + ci) * 27 + k];
    }
    if (tid < 2 * CO_TILE) red[tid] = 0.f;
    __syncthreads();

    const float* xb = x + (size_t)b * CIN * DI * SPI;
    const unsigned char* mb = mo + (size_t)b * SPO;

    float s1[CO_TILE], s2[CO_TILE];
    #pragma unroll
    for (int j = 0; j < CO_TILE; j++) { s1[j] = 0.f; s2[j] = 0.f; }

    #pragma unroll 1
    for (int v = 0; v < VPT; ++v) {
        int blk = (blockIdx.x * VPT + v) * 4 + wid;
        if (blk * 128 >= SPO) break;
        int base0[T], h0a[T], d0a[T];
        bool vw0[T], vw2[T];
        #pragma unroll
        for (int o = 0; o < T; o++) {
            int pp = blk * 128 + lane + 32 * o;
            int w = pp % WO;
            int t1 = pp / WO;
            int h = t1 % HO;
            int d = t1 / HO;
            d0a[o] = d * S - 1;
            h0a[o] = h * S - 1;
            base0[o] = (d * S - 1) * SPI + (h * S - 1) * WI + (w * S - 1);
            vw0[o] = (w * S - 1 >= 0);
            vw2[o] = (w * S + 1 < WI);
        }

        float acc[T][CO_TILE];
        #pragma unroll
        for (int o = 0; o < T; o++)
            #pragma unroll
            for (int j = 0; j < CO_TILE; j++) acc[o][j] = 0.f;

        #pragma unroll
        for (int kd = 0; kd < 3; kd++) {
            #pragma unroll
            for (int kh = 0; kh < 3; kh++) {
                int rb[T]; bool rv[T];
                #pragma unroll
                for (int o = 0; o < T; o++) {
                    rv[o] = ((unsigned)(d0a[o] + kd) < (unsigned)DI) &&
                            ((unsigned)(h0a[o] + kh) < (unsigned)HI);
                    rb[o] = base0[o] + kd * SPI + kh * WI;
                }
                const float* wt = ws + (kd*3 + kh) * 3 * (CIN * CO_TILE);
                #pragma unroll 4
                for (int ci = 0; ci < CIN; ci++) {
                    const float* xr = xb + (size_t)ci * (DI * SPI);
                    #pragma unroll
                    for (int kw = 0; kw < 3; kw++) {
                        float xx[T];
                        #pragma unroll
                        for (int o = 0; o < T; o++) {
                            bool vv = rv[o] && (kw == 1 || (kw == 0 ? vw0[o] : vw2[o]));
                            xx[o] = vv ? __ldg(xr + rb[o] + kw) : 0.f;
                        }
                        const float4* wv = (const float4*)(wt + kw * (CIN*CO_TILE) + ci * CO_TILE);
                        #pragma unroll
                        for (int j = 0; j < CO_TILE / 4; j++) {
                            float4 w4 = wv[j];
                            #pragma unroll
                            for (int o = 0; o < T; o++) {
                                acc[o][4*j+0] += xx[o] * w4.x;
                                acc[o][4*j+1] += xx[o] * w4.y;
                                acc[o][4*j+2] += xx[o] * w4.z;
                                acc[o][4*j+3] += xx[o] * w4.w;
                            }
                        }
                    }
                }
            }
        }

        #pragma unroll
        for (int o = 0; o < T; o++) {
            int pp = blk * 128 + lane + 32 * o;
            float mval = mb[pp] ? 1.f : 0.f;
            float* yb = y + (size_t)(b * COUT + coBase) * SPO + pp;
            #pragma unroll
            for (int j = 0; j < CO_TILE; j++) {
                float a = acc[o][j];
                yb[(size_t)j * SPO] = a;
                float am = a * mval;
                s1[j] += am;
                s2[j] += am * a;
            }
        }
    }

    #pragma unroll
    for (int j = 0; j < CO_TILE; j++) {
        float v1 = s1[j], v2 = s2[j];
        #pragma unroll
        for (int off = 16; off > 0; off >>= 1) {
            v1 += __shfl_down_sync(0xffffffffu, v1, off);
            v2 += __shfl_down_sync(0xffffffffu, v2, off);
        }
        if (lane == 0) {
            atomicAdd(&red[j], v1);
            atomicAdd(&red[CO_TILE + j], v2);
        }
    }
    __syncthreads();
    if (tid < CO_TILE) {
        atomicAdd(&S1g[coBase + tid], red[tid]);
        atomicAdd(&S2g[coBase + tid], red[CO_TILE + tid]);
    }
}

// --------------------------- BN finalize -----------------------------------
__global__ void finalize_kernel(const float* __restrict__ S1,
                                const float* __restrict__ S2,
                                const float* __restrict__ cnt,
                                const float* __restrict__ g,
                                const float* __restrict__ bt,
                                float* __restrict__ scale,
                                float* __restrict__ bias, int C) {
    int c = threadIdx.x;
    if (c < C) {
        float n = fmaxf(*cnt, 1.f);
        float mean = S1[c] / n;
        float var = S2[c] / n - mean * mean;
        var = fmaxf(var, 0.f);
        float sc = g[c] * rsqrtf(var + 1e-5f);
        scale[c] = sc;
        bias[c] = bt[c] - mean * sc;
    }
}

// ----------------- BN apply + relu + mask (float4) -------------------------
template<int COUT, int SPO>
__global__ void bnrelu_kernel(const float* __restrict__ y,
                              const unsigned char* __restrict__ mo,
                              const float* __restrict__ scale,
                              const float* __restrict__ bias,
                              float* __restrict__ xout) {
    int idx = blockIdx.x * 256 + threadIdx.x;
    const int N4 = 2 * COUT * SPO / 4;
    if (idx >= N4) return;
    int sp4 = idx % (SPO / 4);
    int bc  = idx / (SPO / 4);
    int c   = bc % COUT;
    int b   = bc / COUT;
    uchar4 m4 = *(const uchar4*)(mo + (size_t)b * SPO + (size_t)sp4 * 4);
    float4 v = ((const float4*)y)[idx];
    float sc = scale[c], bi = bias[c];
    v.x = m4.x ? fmaxf(v.x * sc + bi, 0.f) : 0.f;
    v.y = m4.y ? fmaxf(v.y * sc + bi, 0.f) : 0.f;
    v.z = m4.z ? fmaxf(v.z * sc + bi, 0.f) : 0.f;
    v.w = m4.w ? fmaxf(v.w * sc + bi, 0.f) : 0.f;
    ((float4*)xout)[idx] = v;
}

// --------------------------- global masked pooling -------------------------
__global__ void pool_kernel(const float* __restrict__ x,
                            const float* __restrict__ cntb,
                            float* __restrict__ gf) {
    __shared__ float sm[256];
    int bc = blockIdx.x;
    int b = bc / 128;
    const float* p = x + (size_t)bc * SP3;
    float s = 0.f;
    for (int i = threadIdx.x; i < SP3; i += 256) s += p[i];
    sm[threadIdx.x] = s;
    __syncthreads();
    for (int off = 128; off > 0; off >>= 1) {
        if (threadIdx.x < off) sm[threadIdx.x] += sm[threadIdx.x + off];
        __syncthreads();
    }
    if (threadIdx.x == 0) gf[bc] = sm[0] / fmaxf(cntb[b], 1.f);
}

// ---------------------------------------------------------------------------
extern "C" void kernel_launch(void* const* d_in, const int* in_sizes, int n_in,
                              void* d_out, int out_size) {
    const float* features = (const float*)d_in[0];
    const int*   mask     = (const int*)d_in[1];
    const float* w0 = (const float*)d_in[2];
    const float* gg0 = (const float*)d_in[3];
    const float* bb0 = (const float*)d_in[4];
    const float* w1 = (const float*)d_in[5];
    const float* gg1 = (const float*)d_in[6];
    const float* bb1 = (const float*)d_in[7];
    const float* w2 = (const float*)d_in[8];
    const float* gg2 = (const float*)d_in[9];
    const float* bb2 = (const float*)d_in[10];
    const float* w3 = (const float*)d_in[11];
    const float* gg3 = (const float*)d_in[12];
    const float* bb3 = (const float*)d_in[13];
    float* out = (float*)d_out;

    void* p;
    cudaGetSymbolAddress(&p, g_x4);   float4* x4 = (float4*)p;
    cudaGetSymbolAddress(&p, g_y0);   float* y0  = (float*)p;
    cudaGetSymbolAddress(&p, g_y1);   float* y1  = (float*)p;
    cudaGetSymbolAddress(&p, g_y2);   float* y2  = (float*)p;
    cudaGetSymbolAddress(&p, g_y3);   float* y3  = (float*)p;
    cudaGetSymbolAddress(&p, g_m0);   unsigned char* m0 = (unsigned char*)p;
    cudaGetSymbolAddress(&p, g_m1);   unsigned char* m1 = (unsigned char*)p;
    cudaGetSymbolAddress(&p, g_m2);   unsigned char* m2 = (unsigned char*)p;
    cudaGetSymbolAddress(&p, g_m3);   unsigned char* m3 = (unsigned char*)p;
    cudaGetSymbolAddress(&p, g_m4);   unsigned char* m4 = (unsigned char*)p;
    cudaGetSymbolAddress(&p, g_mt);   unsigned char* mt = (unsigned char*)p;
    cudaGetSymbolAddress(&p, g_S1);   float* S1 = (float*)p;
    cudaGetSymbolAddress(&p, g_S2);   float* S2 = (float*)p;
    cudaGetSymbolAddress(&p, g_cnt);  float* cnt = (float*)p;
    cudaGetSymbolAddress(&p, g_cntb); float* cntb = (float*)p;
    cudaGetSymbolAddress(&p, g_scale);float* scale = (float*)p;
    cudaGetSymbolAddress(&p, g_bias); float* bias  = (float*)p;

    // (1) fused premask + mask->uchar + stats zero
    fusedpre_kernel<<<(2*SP0/4 + 255) / 256, 256>>>(features, mask, x4, m0);

    // ---------------- block 0: 4 -> 16, stride 1 ----------------
    maskW_kernel<1,192,192><<<(2*32*192*48 + 255)/256, 256>>>(m0, mt, 2*32*192);
    maskDH_kernel<1,32,192,32,192,192,false>
        <<<(2*32*192*48 + 255)/256, 256>>>(mt, m1, &cnt[0], cntb);
    // warp-blocks per batch image = SP0/128 = 9216; grid.x = 9216/(4*VPT=16) = 576
    conv0_kernel<<<dim3(576, 2, 2), 128>>>(x4, m1, w0, y0, &S1[0], &S2[0]);
    finalize_kernel<<<1, 128>>>(&S1[0], &S2[0], &cnt[0], gg0, bb0,
                                &scale[0], &bias[0], 16);
    bnrelu_kernel<16, SP0><<<(2*16*SP0/4 + 255)/256, 256>>>(y0, m1, &scale[0], &bias[0], y0);

    // ---------------- block 1: 16 -> 32, stride 2 ----------------
    maskW_kernel<2,192,96><<<(2*32*192*24 + 255)/256, 256>>>(m1, mt, 2*32*192);
    maskDH_kernel<2,32,192,16,96,96,false>
        <<<(2*16*96*24 + 255)/256, 256>>>(mt, m2, &cnt[1], cntb);
    // warp-blocks = SP1/128 = 1152; VPT=2 -> grid.x = 1152/8 = 144
    conv_kernel<16,32,8,2,32,192,192,16,96,96,2>
        <<<dim3(144, 4, 2), 128, (27*16*8 + 16)*4>>>(
            y0, m2, w1, y1, &S1[128], &S2[128]);
    finalize_kernel<<<1, 128>>>(&S1[128], &S2[128], &cnt[1], gg1, bb1,
                                &scale[128], &bias[128], 32);
    bnrelu_kernel<32, SP1><<<(2*32*SP1/4 + 255)/256, 256>>>(y1, m2, &scale[128], &bias[128], y1);

    // ---------------- block 2: 32 -> 64, stride 2 ----------------
    maskW_kernel<2,96,48><<<(2*16*96*12 + 255)/256, 256>>>(m2, mt, 2*16*96);
    maskDH_kernel<2,16,96,8,48,48,false>
        <<<(2*8*48*12 + 255)/256, 256>>>(mt, m3, &cnt[2], cntb);
    // warp-blocks = SP2/128 = 144; VPT=1 -> grid.x = 36
    conv_kernel<32,64,8,2,16,96,96,8,48,48,1>
        <<<dim3(36, 8, 2), 128, (27*32*8 + 16)*4>>>(
            y1, m3, w2, y2, &S1[256], &S2[256]);
    finalize_kernel<<<1, 128>>>(&S1[256], &S2[256], &cnt[2], gg2, bb2,
                                &scale[256], &bias[256], 64);
    bnrelu_kernel<64, SP2><<<(2*64*SP2/4 + 255)/256, 256>>>(y2, m3, &scale[256], &bias[256], y2);

    // ---------------- block 3: 64 -> 128, stride 2 ----------------
    maskW_kernel<2,48,24><<<(2*8*48*6 + 255)/256, 256>>>(m3, mt, 2*8*48);
    maskDH_kernel<2,8,48,4,24,24,true>
        <<<(2*4*24*6 + 255)/256, 256>>>(mt, m4, &cnt[3], cntb);
    // warp-blocks = SP3/128 = 18; VPT=1 -> grid.x = ceil(18/4) = 5 (guarded)
    conv_kernel<64,128,4,2,8,48,48,4,24,24,1>
        <<<dim3(5, 32, 2), 128, (27*64*4 + 8)*4>>>(
            y2, m4, w3, y3, &S1[384], &S2[384]);
    finalize_kernel<<<1, 128>>>(&S1[384], &S2[384], &cnt[3], gg3, bb3,
                                &scale[384], &bias[384], 128);
    bnrelu_kernel<128, SP3><<<(2*128*SP3/4 + 255)/256, 256>>>(y3, m4, &scale[384], &bias[384], out);

    // ---------------- global pooling ----------------
    pool_kernel<<<256, 256>>>(out, cntb, out + 2*128*SP3);
}

// round 15
// speedup vs baseline: 1.3198x; 1.0843x over previous
#include <cuda_runtime.h>
#include <cuda_bf16.h>
#include <cstdint>

// ---------------------------------------------------------------------------
// SECONDBackbone: 4 x (3x3x3 conv + masked BN + ReLU), strides 1,2,2,2
// B=2. Channels 4->16->32->64->128. Spatial 32x192x192 -> ... -> 4x24x24.
// All conv inputs channel-quad interleaved ([b][ci/4][sp] float4): one
// LDG.128 = 4 channels, lane-consecutive sp (coalesced). Warp = 128
// consecutive flat outputs, thread owns p = base+lane+32*o. BN+ReLU pass
// re-blocks activations for the next conv (same bytes).
// ---------------------------------------------------------------------------

#define SP0 (32*192*192)   // 1,179,648
#define SP1 (16*96*96)     // 147,456
#define SP2 (8*48*48)      // 18,432
#define SP3 (4*24*24)      // 2,304

// Scratch (device globals; allocation-free kernel_launch)
__device__ float4 g_x4 [2*SP0];             // conv0 input, ci-interleaved (CIQ=1)
__device__ float g_y0 [2*16*SP0];           // planar conv outputs (stats+bnrelu)
__device__ float g_y1 [2*32*SP1];
__device__ float g_y2 [2*64*SP2];
__device__ float g_y3 [2*128*SP3];
__device__ float4 g_xq1[2*4*SP1*0 + 2*4*SP0];  // conv1 input: [b][4][SP0] float4
__device__ float4 g_xq2[2*8*SP1];              // conv2 input: [b][8][SP1]
__device__ float4 g_xq3[2*16*SP2];             // conv3 input: [b][16][SP2]
__device__ unsigned char g_m0[2*SP0];
__device__ unsigned char g_m1[2*SP0];
__device__ unsigned char g_m2[2*SP1];
__device__ unsigned char g_m3[2*SP2];
__device__ unsigned char g_m4[2*SP3];
__device__ unsigned char g_mt[2*SP0];       // W-pass temp
__device__ float g_S1[4][128];
__device__ float g_S2[4][128];
__device__ float g_cnt[4];
__device__ float g_cntb[2];
__device__ float g_scale[4][128];
__device__ float g_bias[4][128];

// ---- fused: premask (-> interleaved float4) + mask->uchar + zero stats ----
__global__ void fusedpre_kernel(const float* __restrict__ f,
                                const int* __restrict__ m,
                                float4* __restrict__ x4,
                                unsigned char* __restrict__ m0) {
    int idx = blockIdx.x * 256 + threadIdx.x;      // one thread = 4 voxels
    if (blockIdx.x == 0) {
        int i = threadIdx.x;
        if (i < 128) {
            g_S1[0][i]=0.f; g_S1[1][i]=0.f; g_S1[2][i]=0.f; g_S1[3][i]=0.f;
            g_S2[0][i]=0.f; g_S2[1][i]=0.f; g_S2[2][i]=0.f; g_S2[3][i]=0.f;
        }
        if (i < 4) g_cnt[i] = 0.f;
        if (i < 2) g_cntb[i] = 0.f;
    }
    const int N4 = 2 * SP0 / 4;
    if (idx >= N4) return;
    int sp4 = idx % (SP0 / 4);
    int b   = idx / (SP0 / 4);
    const int4 mi = *(const int4*)(m + (size_t)b * SP0 + (size_t)sp4 * 4);
    uchar4 u;
    u.x = (unsigned char)(mi.x ? 1 : 0);
    u.y = (unsigned char)(mi.y ? 1 : 0);
    u.z = (unsigned char)(mi.z ? 1 : 0);
    u.w = (unsigned char)(mi.w ? 1 : 0);
    ((uchar4*)m0)[idx] = u;
    const float* fb = f + (size_t)b * 4 * SP0 + (size_t)sp4 * 4;
    float4 c0 = *(const float4*)(fb);
    float4 c1 = *(const float4*)(fb + SP0);
    float4 c2 = *(const float4*)(fb + 2 * SP0);
    float4 c3 = *(const float4*)(fb + 3 * SP0);
    float4* xo = x4 + (size_t)b * SP0 + (size_t)sp4 * 4;
    float z0 = mi.x ? 1.f : 0.f, z1 = mi.y ? 1.f : 0.f;
    float z2 = mi.z ? 1.f : 0.f, z3 = mi.w ? 1.f : 0.f;
    xo[0] = make_float4(c0.x*z0, c1.x*z0, c2.x*z0, c3.x*z0);
    xo[1] = make_float4(c0.y*z1, c1.y*z1, c2.y*z1, c3.y*z1);
    xo[2] = make_float4(c0.z*z2, c1.z*z2, c2.z*z2, c3.z*z2);
    xo[3] = make_float4(c0.w*z3, c1.w*z3, c2.w*z3, c3.w*z3);
}

// ------------------- mask maxpool: separable packed OR ---------------------
template<int S, int WI, int WO>
__global__ void maskW_kernel(const unsigned char* __restrict__ min,
                             unsigned char* __restrict__ wt, int nRows) {
    const int WPR = WO / 4;
    int idx = blockIdx.x * 256 + threadIdx.x;
    if (idx >= nRows * WPR) return;
    int k = idx % WPR;
    int rowid = idx / WPR;
    const unsigned char* row = min + (size_t)rowid * WI;
    unsigned out;
    if (S == 1) {
        unsigned x  = ((const unsigned*)row)[k];
        unsigned lb = (k > 0)          ? row[4*k - 1] : 0u;
        unsigned rb = (4*k + 4 < WI)   ? row[4*k + 4] : 0u;
        out = x | ((x << 8) | lb) | ((x >> 8) | (rb << 24));
    } else {
        unsigned x0 = ((const unsigned*)row)[2*k];
        unsigned x1 = ((const unsigned*)row)[2*k + 1];
        unsigned long long v  = ((unsigned long long)x1 << 32) | x0;
        unsigned long long lb = (k > 0) ? (unsigned long long)row[8*k - 1] : 0ull;
        unsigned long long t  = v | (v >> 8) | ((v << 8) | lb);
        out = __byte_perm((unsigned)t, (unsigned)(t >> 32), 0x6420);
    }
    ((unsigned*)wt)[idx] = out;
}

template<int S, int DI, int HI, int DO, int HO, int WO, bool PB>
__global__ void maskDH_kernel(const unsigned char* __restrict__ wt,
                              unsigned char* __restrict__ mout,
                              float* __restrict__ cnt,
                              float* __restrict__ cntb) {
    const int WPR = WO / 4;
    const int N = 2 * DO * HO * WPR;
    int idx = blockIdx.x * 256 + threadIdx.x;
    bool act = idx < N;
    unsigned acc = 0;
    int b = 0;
    if (act) {
        int k  = idx % WPR;
        int r  = idx / WPR;
        int ho = r % HO;
        int r2 = r / HO;
        int dO = r2 % DO;
        b      = r2 / DO;
        int d0 = dO * S - 1, h0 = ho * S - 1;
        #pragma unroll
        for (int kd = 0; kd < 3; kd++) {
            int di = d0 + kd; if ((unsigned)di >= (unsigned)DI) continue;
            #pragma unroll
            for (int kh = 0; kh < 3; kh++) {
                int hi = h0 + kh; if ((unsigned)hi >= (unsigned)HI) continue;
                acc |= ((const unsigned*)(wt +
                        (((size_t)(b * DI + di)) * HI + hi) * WO))[k];
            }
        }
        ((unsigned*)mout)[idx] = acc;
    }
    int c = act ? __popc(acc) : 0;
    #pragma unroll
    for (int off = 16; off > 0; off >>= 1)
        c += __shfl_down_sync(0xffffffffu, c, off);
    if ((threadIdx.x & 31) == 0 && c) {
        atomicAdd(cnt, (float)c);
        if (PB) atomicAdd(&cntb[b], (float)c);
    }
}

// ------- conv0: CIQ=1 interleaved float4, coalesced interleaved T=4 --------
// (uncapped: R12 config, measured fastest for this layer)
__global__ __launch_bounds__(128)
void conv0_kernel(const float4* __restrict__ x4,
                  const unsigned char* __restrict__ mo,
                  const float* __restrict__ wglob,
                  float* __restrict__ y,
                  float* __restrict__ S1g,
                  float* __restrict__ S2g) {
    constexpr int DI=32, HI=192, WI=192, HO=192, WO=192;
    constexpr int T = 4, CO_TILE = 8, VPT = 4;
    constexpr int SPI = HI * WI;
    constexpr int SPO = DI * SPI;

    __shared__ float ws[27*4*CO_TILE];
    __shared__ float red[2*CO_TILE];
    const int tid = threadIdx.x, wid = tid >> 5, lane = tid & 31;
    const int b = blockIdx.z;
    const int coBase = blockIdx.y * CO_TILE;

    for (int i = tid; i < 27*4*CO_TILE; i += 128) {
        int co = i % CO_TILE;
        int rest = i / CO_TILE;
        int ci = rest % 4;
        int k  = rest / 4;
        ws[i] = wglob[((size_t)(coBase + co) * 4 + ci) * 27 + k];
    }
    if (tid < 2*CO_TILE) red[tid] = 0.f;
    __syncthreads();

    const float4* xb = x4 + (size_t)b * SPO;
    const unsigned char* mb = mo + (size_t)b * SPO;

    float s1[CO_TILE], s2[CO_TILE];
    #pragma unroll
    for (int j = 0; j < CO_TILE; j++) { s1[j] = 0.f; s2[j] = 0.f; }

    #pragma unroll 1
    for (int v = 0; v < VPT; ++v) {
        int blk = (blockIdx.x * VPT + v) * 4 + wid;
        int base0[T], h0a[T], d0a[T];
        bool vw0[T], vw2[T];
        #pragma unroll
        for (int o = 0; o < T; o++) {
            int pp = blk * 128 + lane + 32 * o;
            int w = pp % WO;
            int t1 = pp / WO;
            int h = t1 % HO;
            int d = t1 / HO;
            d0a[o] = d - 1;
            h0a[o] = h - 1;
            base0[o] = (d - 1) * SPI + (h - 1) * WI + (w - 1);
            vw0[o] = (w > 0);
            vw2[o] = (w < WO - 1);
        }

        float acc[T][CO_TILE];
        #pragma unroll
        for (int o = 0; o < T; o++)
            #pragma unroll
            for (int j = 0; j < CO_TILE; j++) acc[o][j] = 0.f;

        #pragma unroll
        for (int kd = 0; kd < 3; kd++) {
            #pragma unroll
            for (int kh = 0; kh < 3; kh++) {
                int rb[T]; bool rv[T];
                #pragma unroll
                for (int o = 0; o < T; o++) {
                    rv[o] = ((unsigned)(d0a[o] + kd) < (unsigned)DI) &&
                            ((unsigned)(h0a[o] + kh) < (unsigned)HI);
                    rb[o] = base0[o] + kd * SPI + kh * WI;
                }
                const float* wt = ws + (kd*3 + kh) * 3 * (4*CO_TILE);
                #pragma unroll
                for (int kw = 0; kw < 3; kw++) {
                    float4 xq[T];
                    #pragma unroll
                    for (int o = 0; o < T; o++) {
                        bool vv = rv[o] && (kw == 1 || (kw == 0 ? vw0[o] : vw2[o]));
                        xq[o] = vv ? __ldg(xb + rb[o] + kw)
                                   : make_float4(0.f, 0.f, 0.f, 0.f);
                    }
                    #pragma unroll
                    for (int ci = 0; ci < 4; ci++) {
                        const float4* wv = (const float4*)(wt + kw * (4*CO_TILE) + ci * CO_TILE);
                        float xx[T];
                        #pragma unroll
                        for (int o = 0; o < T; o++)
                            xx[o] = (ci == 0) ? xq[o].x : (ci == 1) ? xq[o].y
                                  : (ci == 2) ? xq[o].z : xq[o].w;
                        #pragma unroll
                        for (int j = 0; j < CO_TILE/4; j++) {
                            float4 w4 = wv[j];
                            #pragma unroll
                            for (int o = 0; o < T; o++) {
                                acc[o][4*j+0] += xx[o] * w4.x;
                                acc[o][4*j+1] += xx[o] * w4.y;
                                acc[o][4*j+2] += xx[o] * w4.z;
                                acc[o][4*j+3] += xx[o] * w4.w;
                            }
                        }
                    }
                }
            }
        }

        #pragma unroll
        for (int o = 0; o < T; o++) {
            int pp = blk * 128 + lane + 32 * o;
            float mval = mb[pp] ? 1.f : 0.f;
            float* yb = y + (size_t)(b * 16 + coBase) * SPO + pp;
            #pragma unroll
            for (int j = 0; j < CO_TILE; j++) {
                float a = acc[o][j];
                yb[(size_t)j * SPO] = a;
                float am = a * mval;
                s1[j] += am;
                s2[j] += am * a;
            }
        }
    }

    #pragma unroll
    for (int j = 0; j < CO_TILE; j++) {
        float v1 = s1[j], v2 = s2[j];
        #pragma unroll
        for (int off = 16; off > 0; off >>= 1) {
            v1 += __shfl_down_sync(0xffffffffu, v1, off);
            v2 += __shfl_down_sync(0xffffffffu, v2, off);
        }
        if (lane == 0) {
            atomicAdd(&red[j], v1);
            atomicAdd(&red[CO_TILE + j], v2);
        }
    }
    __syncthreads();
    if (tid < CO_TILE) {
        atomicAdd(&S1g[coBase + tid], red[tid]);
        atomicAdd(&S2g[coBase + tid], red[CO_TILE + tid]);
    }
}

// ---- convq: channel-quad interleaved input [b][cq][sp] float4, any S ------
template<int CIQ, int COUT, int CO_TILE, int S,
         int DI, int HI, int WI, int DO, int HO, int WO, int VPT>
__global__ __launch_bounds__(128, 4)
void convq_kernel(const float4* __restrict__ xq,
                  const unsigned char* __restrict__ mo,
                  const float* __restrict__ wglob,
                  float* __restrict__ y,
                  float* __restrict__ S1g,
                  float* __restrict__ S2g) {
    constexpr int T = 4;
    constexpr int CIN = 4 * CIQ;
    constexpr int SPO = DO * HO * WO;
    constexpr int SPI = HI * WI;

    extern __shared__ float sh[];
    float* ws  = sh;                            // [27][CIN][CO_TILE]
    float* red = sh + 27 * CIN * CO_TILE;
    const int tid = threadIdx.x, wid = tid >> 5, lane = tid & 31;
    const int b = blockIdx.z;
    const int coBase = blockIdx.y * CO_TILE;

    for (int i = tid; i < 27 * CIN * CO_TILE; i += 128) {
        int co = i % CO_TILE;
        int rest = i / CO_TILE;
        int ci = rest % CIN;
        int k  = rest / CIN;
        ws[i] = wglob[((size_t)(coBase + co) * CIN + ci) * 27 + k];
    }
    if (tid < 2 * CO_TILE) red[tid] = 0.f;
    __syncthreads();

    const float4* xb = xq + (size_t)b * CIQ * DI * SPI;
    const unsigned char* mb = mo + (size_t)b * SPO;

    float s1[CO_TILE], s2[CO_TILE];
    #pragma unroll
    for (int j = 0; j < CO_TILE; j++) { s1[j] = 0.f; s2[j] = 0.f; }

    #pragma unroll 1
    for (int v = 0; v < VPT; ++v) {
        int blk = (blockIdx.x * VPT + v) * 4 + wid;
        if (blk * 128 >= SPO) break;
        int base0[T], h0a[T], d0a[T];
        bool vw0[T], vw2[T];
        #pragma unroll
        for (int o = 0; o < T; o++) {
            int pp = blk * 128 + lane + 32 * o;
            int w = pp % WO;
            int t1 = pp / WO;
            int h = t1 % HO;
            int d = t1 / HO;
            d0a[o] = d * S - 1;
            h0a[o] = h * S - 1;
            base0[o] = (d * S - 1) * SPI + (h * S - 1) * WI + (w * S - 1);
            vw0[o] = (w * S - 1 >= 0);
            vw2[o] = (w * S + 1 < WI);
        }

        float acc[T][CO_TILE];
        #pragma unroll
        for (int o = 0; o < T; o++)
            #pragma unroll
            for (int j = 0; j < CO_TILE; j++) acc[o][j] = 0.f;

        #pragma unroll
        for (int kd = 0; kd < 3; kd++) {
            #pragma unroll
            for (int kh = 0; kh < 3; kh++) {
                int rb[T]; bool rv[T];
                #pragma unroll
                for (int o = 0; o < T; o++) {
                    rv[o] = ((unsigned)(d0a[o] + kd) < (unsigned)DI) &&
                            ((unsigned)(h0a[o] + kh) < (unsigned)HI);
                    rb[o] = base0[o] + kd * SPI + kh * WI;
                }
                const float* wt = ws + (kd*3 + kh) * 3 * (CIN * CO_TILE);
                #pragma unroll 2
                for (int cq = 0; cq < CIQ; cq++) {
                    const float4* xr = xb + (size_t)cq * (DI * SPI);
                    #pragma unroll
                    for (int kw = 0; kw < 3; kw++) {
                        float4 xv[T];
                        #pragma unroll
                        for (int o = 0; o < T; o++) {
                            bool vv = rv[o] && (kw == 1 || (kw == 0 ? vw0[o] : vw2[o]));
                            xv[o] = vv ? __ldg(xr + rb[o] + kw)
                                       : make_float4(0.f, 0.f, 0.f, 0.f);
                        }
                        #pragma unroll
                        for (int comp = 0; comp < 4; comp++) {
                            const float4* wv = (const float4*)(
                                wt + kw * (CIN*CO_TILE) + (cq*4 + comp) * CO_TILE);
                            float xx[T];
                            #pragma unroll
                            for (int o = 0; o < T; o++)
                                xx[o] = (comp == 0) ? xv[o].x : (comp == 1) ? xv[o].y
                                      : (comp == 2) ? xv[o].z : xv[o].w;
                            #pragma unroll
                            for (int j = 0; j < CO_TILE / 4; j++) {
                                float4 w4 = wv[j];
                                #pragma unroll
                                for (int o = 0; o < T; o++) {
                                    acc[o][4*j+0] += xx[o] * w4.x;
                                    acc[o][4*j+1] += xx[o] * w4.y;
                                    acc[o][4*j+2] += xx[o] * w4.z;
                                    acc[o][4*j+3] += xx[o] * w4.w;
                                }
                            }
                        }
                    }
                }
            }
        }

        #pragma unroll
        for (int o = 0; o < T; o++) {
            int pp = blk * 128 + lane + 32 * o;
            float mval = mb[pp] ? 1.f : 0.f;
            float* yb = y + (size_t)(b * COUT + coBase) * SPO + pp;
            #pragma unroll
            for (int j = 0; j < CO_TILE; j++) {
                float a = acc[o][j];
                yb[(size_t)j * SPO] = a;
                float am = a * mval;
                s1[j] += am;
                s2[j] += am * a;
            }
        }
    }

    #pragma unroll
    for (int j = 0; j < CO_TILE; j++) {
        float v1 = s1[j], v2 = s2[j];
        #pragma unroll
        for (int off = 16; off > 0; off >>= 1) {
            v1 += __shfl_down_sync(0xffffffffu, v1, off);
            v2 += __shfl_down_sync(0xffffffffu, v2, off);
        }
        if (lane == 0) {
            atomicAdd(&red[j], v1);
            atomicAdd(&red[CO_TILE + j], v2);
        }
    }
    __syncthreads();
    if (tid < CO_TILE) {
        atomicAdd(&S1g[coBase + tid], red[tid]);
        atomicAdd(&S2g[coBase + tid], red[CO_TILE + tid]);
    }
}

// --------------------------- BN finalize -----------------------------------
__global__ void finalize_kernel(const float* __restrict__ S1,
                                const float* __restrict__ S2,
                                const float* __restrict__ cnt,
                                const float* __restrict__ g,
                                const float* __restrict__ bt,
                                float* __restrict__ scale,
                                float* __restrict__ bias, int C) {
    int c = threadIdx.x;
    if (c < C) {
        float n = fmaxf(*cnt, 1.f);
        float mean = S1[c] / n;
        float var = S2[c] / n - mean * mean;
        var = fmaxf(var, 0.f);
        float sc = g[c] * rsqrtf(var + 1e-5f);
        scale[c] = sc;
        bias[c] = bt[c] - mean * sc;
    }
}

// --- BN apply + relu + mask, emits channel-quad interleaved next-input -----
template<int COUT, int SPO>
__global__ void bnreluq_kernel(const float* __restrict__ y,
                               const unsigned char* __restrict__ mo,
                               const float* __restrict__ scale,
                               const float* __restrict__ bias,
                               float4* __restrict__ xq) {
    constexpr int CQ = COUT / 4;
    int idx = blockIdx.x * 256 + threadIdx.x;       // one thread = 1 sp x 4 ch
    const int N = 2 * CQ * SPO;
    if (idx >= N) return;
    int sp  = idx % SPO;
    int r   = idx / SPO;
    int cq  = r % CQ;
    int b   = r / CQ;
    float m = mo[(size_t)b * SPO + sp] ? 1.f : 0.f;
    const float* yb = y + ((size_t)(b * COUT + cq * 4)) * SPO + sp;
    float4 v;
    v.x = fmaxf(yb[0]            * scale[cq*4+0] + bias[cq*4+0], 0.f) * m;
    v.y = fmaxf(yb[(size_t)SPO]  * scale[cq*4+1] + bias[cq*4+1], 0.f) * m;
    v.z = fmaxf(yb[(size_t)2*SPO]* scale[cq*4+2] + bias[cq*4+2], 0.f) * m;
    v.w = fmaxf(yb[(size_t)3*SPO]* scale[cq*4+3] + bias[cq*4+3], 0.f) * m;
    xq[((size_t)(b * CQ + cq)) * SPO + sp] = v;
}

// ----------------- final BN apply + relu + mask (planar, float4) -----------
template<int COUT, int SPO>
__global__ void bnrelu_kernel(const float* __restrict__ y,
                              const unsigned char* __restrict__ mo,
                              const float* __restrict__ scale,
                              const float* __restrict__ bias,
                              float* __restrict__ xout) {
    int idx = blockIdx.x * 256 + threadIdx.x;
    const int N4 = 2 * COUT * SPO / 4;
    if (idx >= N4) return;
    int sp4 = idx % (SPO / 4);
    int bc  = idx / (SPO / 4);
    int c   = bc % COUT;
    int b   = bc / COUT;
    uchar4 m4 = *(const uchar4*)(mo + (size_t)b * SPO + (size_t)sp4 * 4);
    float4 v = ((const float4*)y)[idx];
    float sc = scale[c], bi = bias[c];
    v.x = m4.x ? fmaxf(v.x * sc + bi, 0.f) : 0.f;
    v.y = m4.y ? fmaxf(v.y * sc + bi, 0.f) : 0.f;
    v.z = m4.z ? fmaxf(v.z * sc + bi, 0.f) : 0.f;
    v.w = m4.w ? fmaxf(v.w * sc + bi, 0.f) : 0.f;
    ((float4*)xout)[idx] = v;
}

// --------------------------- global masked pooling -------------------------
__global__ void pool_kernel(const float* __restrict__ x,
                            const float* __restrict__ cntb,
                            float* __restrict__ gf) {
    __shared__ float sm[256];
    int bc = blockIdx.x;
    int b = bc / 128;
    const float* p = x + (size_t)bc * SP3;
    float s = 0.f;
    for (int i = threadIdx.x; i < SP3; i += 256) s += p[i];
    sm[threadIdx.x] = s;
    __syncthreads();
    for (int off = 128; off > 0; off >>= 1) {
        if (threadIdx.x < off) sm[threadIdx.x] += sm[threadIdx.x + off];
        __syncthreads();
    }
    if (threadIdx.x == 0) gf[bc] = sm[0] / fmaxf(cntb[b], 1.f);
}

// ---------------------------------------------------------------------------
extern "C" void kernel_launch(void* const* d_in, const int* in_sizes, int n_in,
                              void* d_out, int out_size) {
    const float* features = (const float*)d_in[0];
    const int*   mask     = (const int*)d_in[1];
    const float* w0 = (const float*)d_in[2];
    const float* gg0 = (const float*)d_in[3];
    const float* bb0 = (const float*)d_in[4];
    const float* w1 = (const float*)d_in[5];
    const float* gg1 = (const float*)d_in[6];
    const float* bb1 = (const float*)d_in[7];
    const float* w2 = (const float*)d_in[8];
    const float* gg2 = (const float*)d_in[9];
    const float* bb2 = (const float*)d_in[10];
    const float* w3 = (const float*)d_in[11];
    const float* gg3 = (const float*)d_in[12];
    const float* bb3 = (const float*)d_in[13];
    float* out = (float*)d_out;

    void* p;
    cudaGetSymbolAddress(&p, g_x4);   float4* x4  = (float4*)p;
    cudaGetSymbolAddress(&p, g_xq1);  float4* xq1 = (float4*)p;
    cudaGetSymbolAddress(&p, g_xq2);  float4* xq2 = (float4*)p;
    cudaGetSymbolAddress(&p, g_xq3);  float4* xq3 = (float4*)p;
    cudaGetSymbolAddress(&p, g_y0);   float* y0  = (float*)p;
    cudaGetSymbolAddress(&p, g_y1);   float* y1  = (float*)p;
    cudaGetSymbolAddress(&p, g_y2);   float* y2  = (float*)p;
    cudaGetSymbolAddress(&p, g_y3);   float* y3  = (float*)p;
    cudaGetSymbolAddress(&p, g_m0);   unsigned char* m0 = (unsigned char*)p;
    cudaGetSymbolAddress(&p, g_m1);   unsigned char* m1 = (unsigned char*)p;
    cudaGetSymbolAddress(&p, g_m2);   unsigned char* m2 = (unsigned char*)p;
    cudaGetSymbolAddress(&p, g_m3);   unsigned char* m3 = (unsigned char*)p;
    cudaGetSymbolAddress(&p, g_m4);   unsigned char* m4 = (unsigned char*)p;
    cudaGetSymbolAddress(&p, g_mt);   unsigned char* mt = (unsigned char*)p;
    cudaGetSymbolAddress(&p, g_S1);   float* S1 = (float*)p;
    cudaGetSymbolAddress(&p, g_S2);   float* S2 = (float*)p;
    cudaGetSymbolAddress(&p, g_cnt);  float* cnt = (float*)p;
    cudaGetSymbolAddress(&p, g_cntb); float* cntb = (float*)p;
    cudaGetSymbolAddress(&p, g_scale);float* scale = (float*)p;
    cudaGetSymbolAddress(&p, g_bias); float* bias  = (float*)p;

    // (1) fused premask + mask->uchar + stats zero
    fusedpre_kernel<<<(2*SP0/4 + 255) / 256, 256>>>(features, mask, x4, m0);

    // ---------------- block 0: 4 -> 16, stride 1 ----------------
    maskW_kernel<1,192,192><<<(2*32*192*48 + 255)/256, 256>>>(m0, mt, 2*32*192);
    maskDH_kernel<1,32,192,32,192,192,false>
        <<<(2*32*192*48 + 255)/256, 256>>>(mt, m1, &cnt[0], cntb);
    conv0_kernel<<<dim3(576, 2, 2), 128>>>(x4, m1, w0, y0, &S1[0], &S2[0]);
    finalize_kernel<<<1, 128>>>(&S1[0], &S2[0], &cnt[0], gg0, bb0,
                                &scale[0], &bias[0], 16);
    bnreluq_kernel<16, SP0><<<(2*4*SP0 + 255)/256, 256>>>(
        y0, m1, &scale[0], &bias[0], xq1);

    // ---------------- block 1: 16 -> 32, stride 2 ----------------
    maskW_kernel<2,192,96><<<(2*32*192*24 + 255)/256, 256>>>(m1, mt, 2*32*192);
    maskDH_kernel<2,32,192,16,96,96,false>
        <<<(2*16*96*24 + 255)/256, 256>>>(mt, m2, &cnt[1], cntb);
    convq_kernel<4,32,8,2,32,192,192,16,96,96,2>
        <<<dim3(144, 4, 2), 128, (27*16*8 + 16)*4>>>(
            xq1, m2, w1, y1, &S1[128], &S2[128]);
    finalize_kernel<<<1, 128>>>(&S1[128], &S2[128], &cnt[1], gg1, bb1,
                                &scale[128], &bias[128], 32);
    bnreluq_kernel<32, SP1><<<(2*8*SP1 + 255)/256, 256>>>(
        y1, m2, &scale[128], &bias[128], xq2);

    // ---------------- block 2: 32 -> 64, stride 2 ----------------
    maskW_kernel<2,96,48><<<(2*16*96*12 + 255)/256, 256>>>(m2, mt, 2*16*96);
    maskDH_kernel<2,16,96,8,48,48,false>
        <<<(2*8*48*12 + 255)/256, 256>>>(mt, m3, &cnt[2], cntb);
    convq_kernel<8,64,8,2,16,96,96,8,48,48,1>
        <<<dim3(36, 8, 2), 128, (27*32*8 + 16)*4>>>(
            xq2, m3, w2, y2, &S1[256], &S2[256]);
    finalize_kernel<<<1, 128>>>(&S1[256], &S2[256], &cnt[2], gg2, bb2,
                                &scale[256], &bias[256], 64);
    bnreluq_kernel<64, SP2><<<(2*16*SP2 + 255)/256, 256>>>(
        y2, m3, &scale[256], &bias[256], xq3);

    // ---------------- block 3: 64 -> 128, stride 2 ----------------
    maskW_kernel<2,48,24><<<(2*8*48*6 + 255)/256, 256>>>(m3, mt, 2*8*48);
    maskDH_kernel<2,8,48,4,24,24,true>
        <<<(2*4*24*6 + 255)/256, 256>>>(mt, m4, &cnt[3], cntb);
    convq_kernel<16,128,4,2,8,48,48,4,24,24,1>
        <<<dim3(5, 32, 2), 128, (27*64*4 + 8)*4>>>(
            xq3, m4, w3, y3, &S1[384], &S2[384]);
    finalize_kernel<<<1, 128>>>(&S1[384], &S2[384], &cnt[3], gg3, bb3,
                                &scale[384], &bias[384], 128);
    bnrelu_kernel<128, SP3><<<(2*128*SP3/4 + 255)/256, 256>>>(
        y3, m4, &scale[384], &bias[384], out);

    // ---------------- global pooling ----------------
    pool_kernel<<<256, 256>>>(out, cntb, out + 2*128*SP3);
}